// round 2
// baseline (speedup 1.0000x reference)
#include <cuda_runtime.h>
#include <math.h>
#include <stdint.h>

#define DIM    1024
#define NH     16
#define HD     64
#define LATENT 128
#define QRANK  256
#define BATCH  4
#define SEQ    2048
#define NTOK   (BATCH*SEQ)   // 8192

// ---------------- scratch (static device globals; allocation-free rule) ---------
__device__ float g_kvl [(size_t)NTOK * LATENT];        //  4 MB
__device__ float g_kvup[(size_t)NTOK * 2 * DIM];       // 64 MB  (K | V interleaved per row)
__device__ float g_qc  [(size_t)NTOK * QRANK];         //  8 MB
__device__ float g_q   [(size_t)NTOK * DIM];           // 32 MB
__device__ float g_ctx [(size_t)NTOK * DIM];           // 32 MB

// ---------------- generic tiled SGEMM:  C[M,N] = A[M,K] @ W[K,N] + bias --------
// BM=BN=64, BK=16, 256 threads, 4x4 microtile per thread.
__global__ __launch_bounds__(256) void sgemm_bias(
    const float* __restrict__ A, const float* __restrict__ W,
    const float* __restrict__ bias, float* __restrict__ C,
    int M, int N, int K)
{
    __shared__ float As[64][20];   // [m][k], row stride 20 floats = 80B (16B aligned, bank-skewed)
    __shared__ float Ws[16][64];   // [k][n]

    const int tid = threadIdx.x;
    const int tx = tid & 15, ty = tid >> 4;
    const int row0 = blockIdx.y * 64, col0 = blockIdx.x * 64;

    const int ar = tid >> 2, ac = (tid & 3) * 4;     // A-tile loader coords
    const int wr = tid >> 4, wc = (tid & 15) * 4;    // W-tile loader coords

    float acc[4][4] = {};

    for (int k0 = 0; k0 < K; k0 += 16) {
        float4 av = *(const float4*)(A + (size_t)(row0 + ar) * K + k0 + ac);
        float4 wv = *(const float4*)(W + (size_t)(k0 + wr) * N + col0 + wc);
        *(float4*)&As[ar][ac] = av;
        *(float4*)&Ws[wr][wc] = wv;
        __syncthreads();

        #pragma unroll
        for (int kk = 0; kk < 16; kk++) {
            float a0 = As[ty*4+0][kk];
            float a1 = As[ty*4+1][kk];
            float a2 = As[ty*4+2][kk];
            float a3 = As[ty*4+3][kk];
            float4 bv = *(const float4*)&Ws[kk][tx*4];
            acc[0][0] = fmaf(a0, bv.x, acc[0][0]); acc[0][1] = fmaf(a0, bv.y, acc[0][1]);
            acc[0][2] = fmaf(a0, bv.z, acc[0][2]); acc[0][3] = fmaf(a0, bv.w, acc[0][3]);
            acc[1][0] = fmaf(a1, bv.x, acc[1][0]); acc[1][1] = fmaf(a1, bv.y, acc[1][1]);
            acc[1][2] = fmaf(a1, bv.z, acc[1][2]); acc[1][3] = fmaf(a1, bv.w, acc[1][3]);
            acc[2][0] = fmaf(a2, bv.x, acc[2][0]); acc[2][1] = fmaf(a2, bv.y, acc[2][1]);
            acc[2][2] = fmaf(a2, bv.z, acc[2][2]); acc[2][3] = fmaf(a2, bv.w, acc[2][3]);
            acc[3][0] = fmaf(a3, bv.x, acc[3][0]); acc[3][1] = fmaf(a3, bv.y, acc[3][1]);
            acc[3][2] = fmaf(a3, bv.z, acc[3][2]); acc[3][3] = fmaf(a3, bv.w, acc[3][3]);
        }
        __syncthreads();
    }

    float4 bv = *(const float4*)(bias + col0 + tx*4);
    #pragma unroll
    for (int i = 0; i < 4; i++) {
        size_t r = (size_t)(row0 + ty*4 + i);
        float4 ov;
        ov.x = acc[i][0] + bv.x;
        ov.y = acc[i][1] + bv.y;
        ov.z = acc[i][2] + bv.z;
        ov.w = acc[i][3] + bv.w;
        *(float4*)(C + r * N + col0 + tx*4) = ov;
    }
}

// ---------------- causal flash attention, fp32 ---------------------------------
// grid = (S/64, B*H). CTA: 64 q-rows x full head (hd=64). 256 threads, 16x16 grid,
// 4x4 microtiles for both the score GEMM and the PV GEMM. Online softmax state
// (m, l) replicated across the 16 lanes of each row-group; reduced via shfl.
#define SMS 65   // smem row stride (65 -> stride-1 banks for transposed K store)

__global__ __launch_bounds__(256) void attn_kernel(
    const float* __restrict__ Qm,   // [NTOK, DIM]
    const float* __restrict__ KVm,  // [NTOK, 2*DIM]  (K at +0, V at +DIM)
    float* __restrict__ Ctx)        // [NTOK, DIM]
{
    extern __shared__ float smx[];
    float* Qs  = smx;                 // [64][SMS]  Qs[row][d]
    float* Kts = smx + 64*SMS;        // [64][SMS]  Kts[d][kcol]   (transposed)
    float* Vs  = smx + 2*64*SMS;      // [64][SMS]  Vs[kcol][d]
    float* Ps  = smx + 3*64*SMS;      // [64][SMS]  Ps[row][kcol]

    const int qi  = blockIdx.x;
    const int b   = blockIdx.y >> 4;
    const int h   = blockIdx.y & 15;
    const int tid = threadIdx.x;
    const int tx  = tid & 15, ty = tid >> 4;

    const int qtok0 = b * SEQ + qi * 64;
    const float* Qbase = Qm + (size_t)qtok0 * DIM + h * HD;

    for (int idx = tid; idx < 4096; idx += 256) {
        int r = idx >> 6, d = idx & 63;
        Qs[r*SMS + d] = Qbase[(size_t)r * DIM + d];
    }

    float m_run[4], l_run[4], o[4][4];
    #pragma unroll
    for (int i = 0; i < 4; i++) {
        m_run[i] = -INFINITY; l_run[i] = 0.f;
        #pragma unroll
        for (int j = 0; j < 4; j++) o[i][j] = 0.f;
    }

    for (int kt = 0; kt <= qi; kt++) {
        const float* Kbase = KVm + (size_t)(b * SEQ + kt * 64) * (2*DIM) + h * HD;
        const float* Vbase = Kbase + DIM;
        for (int idx = tid; idx < 4096; idx += 256) {
            int r = idx >> 6, d = idx & 63;
            Kts[d*SMS + r] = Kbase[(size_t)r * (2*DIM) + d];   // transpose-store, stride-1 banks
            Vs [r*SMS + d] = Vbase[(size_t)r * (2*DIM) + d];
        }
        __syncthreads();

        // S = Q @ K^T
        float s[4][4] = {};
        #pragma unroll 8
        for (int d = 0; d < 64; d++) {
            float a0 = Qs[(ty*4+0)*SMS + d];
            float a1 = Qs[(ty*4+1)*SMS + d];
            float a2 = Qs[(ty*4+2)*SMS + d];
            float a3 = Qs[(ty*4+3)*SMS + d];
            float b0 = Kts[d*SMS + tx*4+0];
            float b1 = Kts[d*SMS + tx*4+1];
            float b2 = Kts[d*SMS + tx*4+2];
            float b3 = Kts[d*SMS + tx*4+3];
            s[0][0] = fmaf(a0,b0,s[0][0]); s[0][1] = fmaf(a0,b1,s[0][1]);
            s[0][2] = fmaf(a0,b2,s[0][2]); s[0][3] = fmaf(a0,b3,s[0][3]);
            s[1][0] = fmaf(a1,b0,s[1][0]); s[1][1] = fmaf(a1,b1,s[1][1]);
            s[1][2] = fmaf(a1,b2,s[1][2]); s[1][3] = fmaf(a1,b3,s[1][3]);
            s[2][0] = fmaf(a2,b0,s[2][0]); s[2][1] = fmaf(a2,b1,s[2][1]);
            s[2][2] = fmaf(a2,b2,s[2][2]); s[2][3] = fmaf(a2,b3,s[2][3]);
            s[3][0] = fmaf(a3,b0,s[3][0]); s[3][1] = fmaf(a3,b1,s[3][1]);
            s[3][2] = fmaf(a3,b2,s[3][2]); s[3][3] = fmaf(a3,b3,s[3][3]);
        }

        const float scale = 0.125f;  // 1/sqrt(64)
        const bool diag = (kt == qi);
        #pragma unroll
        for (int i = 0; i < 4; i++) {
            int ri = ty*4 + i;
            #pragma unroll
            for (int j = 0; j < 4; j++) {
                float v = s[i][j] * scale;
                if (diag && (tx*4 + j) > ri) v = -1e30f;   // causal mask within diag tile
                s[i][j] = v;
            }
        }

        // online softmax (per row; 16 lanes per row-group hold 4 cols each)
        #pragma unroll
        for (int i = 0; i < 4; i++) {
            float mx = fmaxf(fmaxf(s[i][0], s[i][1]), fmaxf(s[i][2], s[i][3]));
            mx = fmaxf(mx, __shfl_xor_sync(0xffffffffu, mx, 1));
            mx = fmaxf(mx, __shfl_xor_sync(0xffffffffu, mx, 2));
            mx = fmaxf(mx, __shfl_xor_sync(0xffffffffu, mx, 4));
            mx = fmaxf(mx, __shfl_xor_sync(0xffffffffu, mx, 8));
            float m_new = fmaxf(m_run[i], mx);
            float corr  = __expf(m_run[i] - m_new);
            m_run[i] = m_new;
            float psum = 0.f;
            #pragma unroll
            for (int j = 0; j < 4; j++) {
                float p = __expf(s[i][j] - m_new);
                s[i][j] = p;
                psum += p;
            }
            psum += __shfl_xor_sync(0xffffffffu, psum, 1);
            psum += __shfl_xor_sync(0xffffffffu, psum, 2);
            psum += __shfl_xor_sync(0xffffffffu, psum, 4);
            psum += __shfl_xor_sync(0xffffffffu, psum, 8);
            l_run[i] = l_run[i] * corr + psum;
            #pragma unroll
            for (int j = 0; j < 4; j++) o[i][j] *= corr;
        }

        // stage P to smem for the PV GEMM
        #pragma unroll
        for (int i = 0; i < 4; i++)
            #pragma unroll
            for (int j = 0; j < 4; j++)
                Ps[(ty*4+i)*SMS + tx*4+j] = s[i][j];
        __syncthreads();

        // O += P @ V
        #pragma unroll 8
        for (int kk = 0; kk < 64; kk++) {
            float a0 = Ps[(ty*4+0)*SMS + kk];
            float a1 = Ps[(ty*4+1)*SMS + kk];
            float a2 = Ps[(ty*4+2)*SMS + kk];
            float a3 = Ps[(ty*4+3)*SMS + kk];
            float b0 = Vs[kk*SMS + tx*4+0];
            float b1 = Vs[kk*SMS + tx*4+1];
            float b2 = Vs[kk*SMS + tx*4+2];
            float b3 = Vs[kk*SMS + tx*4+3];
            o[0][0] = fmaf(a0,b0,o[0][0]); o[0][1] = fmaf(a0,b1,o[0][1]);
            o[0][2] = fmaf(a0,b2,o[0][2]); o[0][3] = fmaf(a0,b3,o[0][3]);
            o[1][0] = fmaf(a1,b0,o[1][0]); o[1][1] = fmaf(a1,b1,o[1][1]);
            o[1][2] = fmaf(a1,b2,o[1][2]); o[1][3] = fmaf(a1,b3,o[1][3]);
            o[2][0] = fmaf(a2,b0,o[2][0]); o[2][1] = fmaf(a2,b1,o[2][1]);
            o[2][2] = fmaf(a2,b2,o[2][2]); o[2][3] = fmaf(a2,b3,o[2][3]);
            o[3][0] = fmaf(a3,b0,o[3][0]); o[3][1] = fmaf(a3,b1,o[3][1]);
            o[3][2] = fmaf(a3,b2,o[3][2]); o[3][3] = fmaf(a3,b3,o[3][3]);
        }
        __syncthreads();
    }

    // epilogue: normalize and write ctx
    float* Cbase = Ctx + (size_t)qtok0 * DIM + h * HD;
    #pragma unroll
    for (int i = 0; i < 4; i++) {
        float inv = 1.f / l_run[i];
        float4 ov = make_float4(o[i][0]*inv, o[i][1]*inv, o[i][2]*inv, o[i][3]*inv);
        *(float4*)(Cbase + (size_t)(ty*4 + i) * DIM + tx*4) = ov;
    }
}

// ---------------- launch --------------------------------------------------------
extern "C" void kernel_launch(void* const* d_in, const int* in_sizes, int n_in,
                              void* d_out, int out_size)
{
    const float* x     = (const float*)d_in[0];
    // d_in[1]: mask (causal tril) — implemented structurally, not read
    const float* w_kvc = (const float*)d_in[2];
    const float* b_kvc = (const float*)d_in[3];
    const float* w_kvu = (const float*)d_in[4];
    const float* b_kvu = (const float*)d_in[5];
    const float* w_qc  = (const float*)d_in[6];
    const float* b_qc  = (const float*)d_in[7];
    const float* w_qu  = (const float*)d_in[8];
    const float* b_qu  = (const float*)d_in[9];
    const float* w_o   = (const float*)d_in[10];
    const float* b_o   = (const float*)d_in[11];
    float* out = (float*)d_out;

    float *kvl, *kvup, *qc, *q, *ctx;
    cudaGetSymbolAddress((void**)&kvl,  g_kvl);
    cudaGetSymbolAddress((void**)&kvup, g_kvup);
    cudaGetSymbolAddress((void**)&qc,   g_qc);
    cudaGetSymbolAddress((void**)&q,    g_q);
    cudaGetSymbolAddress((void**)&ctx,  g_ctx);

    const int ATTN_SMEM = 4 * 64 * SMS * (int)sizeof(float);  // 66,560 B
    cudaFuncSetAttribute(attn_kernel, cudaFuncAttributeMaxDynamicSharedMemorySize, ATTN_SMEM);

    dim3 blk(256);

    // 1) kv_latent = x @ w_kvc + b                [8192, 128]
    sgemm_bias<<<dim3(LATENT/64, NTOK/64), blk>>>(x, w_kvc, b_kvc, kvl, NTOK, LATENT, DIM);
    // 2) kv_up = kv_latent @ w_kvu + b            [8192, 2048]  (K | V)
    sgemm_bias<<<dim3(2*DIM/64, NTOK/64), blk>>>(kvl, w_kvu, b_kvu, kvup, NTOK, 2*DIM, LATENT);
    // 3) qc = x @ w_qc + b                        [8192, 256]
    sgemm_bias<<<dim3(QRANK/64, NTOK/64), blk>>>(x, w_qc, b_qc, qc, NTOK, QRANK, DIM);
    // 4) Q = qc @ w_qu + b                        [8192, 1024]
    sgemm_bias<<<dim3(DIM/64, NTOK/64), blk>>>(qc, w_qu, b_qu, q, NTOK, DIM, QRANK);
    // 5) causal attention -> ctx                  [8192, 1024]
    attn_kernel<<<dim3(SEQ/64, BATCH*NH), blk, ATTN_SMEM>>>(q, kvup, ctx);
    // 6) out = ctx @ w_o + b                      [8192, 1024]
    sgemm_bias<<<dim3(DIM/64, NTOK/64), blk>>>(ctx, w_o, b_o, out, NTOK, DIM, DIM);
}

// round 3
// speedup vs baseline: 1.1468x; 1.1468x over previous
#include <cuda_runtime.h>
#include <cuda_bf16.h>
#include <math.h>
#include <stdint.h>

#define DIM    1024
#define NH     16
#define HD     64
#define LATENT 128
#define QRANK  256
#define BATCH  4
#define SEQ    2048
#define NTOK   (BATCH*SEQ)   // 8192

// ---------------- scratch (static device globals; allocation-free rule) ---------
__device__ float g_kvl [(size_t)NTOK * LATENT];        //  4 MB
__device__ float g_kvup[(size_t)NTOK * 2 * DIM];       // 64 MB  (K | V per row)
__device__ float g_qc  [(size_t)NTOK * QRANK];         //  8 MB
__device__ float g_q   [(size_t)NTOK * DIM];           // 32 MB
__device__ float g_ctx [(size_t)NTOK * DIM];           // 32 MB

// ================= split-bf16 tensor-core GEMM =================================
// C[M,N] = A[M,K] @ W[K,N] + bias, fp32 in/out.
// A ~ Ah + Al (bf16), W ~ Wh + Wl (bf16); C = Ah*Wh + Ah*Wl + Al*Wh (fp32 acc).
// CTA tile 128x64, BK=32, 256 threads = 8 warps of 32x32 warp tiles.
#define BM 128
#define BN 64
#define BK 32
#define KP 36   // padded k-stride (bf16 elems): 72B rows, conflict-friendly

__device__ __forceinline__ void mma16816(float* c, const uint32_t* a, const uint32_t* b) {
    asm volatile(
        "mma.sync.aligned.m16n8k16.row.col.f32.bf16.bf16.f32 "
        "{%0,%1,%2,%3}, {%4,%5,%6,%7}, {%8,%9}, {%0,%1,%2,%3};"
        : "+f"(c[0]), "+f"(c[1]), "+f"(c[2]), "+f"(c[3])
        : "r"(a[0]), "r"(a[1]), "r"(a[2]), "r"(a[3]), "r"(b[0]), "r"(b[1]));
}

__global__ __launch_bounds__(256) void gemm_bf16x2(
    const float* __restrict__ A, const float* __restrict__ W,
    const float* __restrict__ bias, float* __restrict__ C,
    int M, int N, int K)
{
    __shared__ __nv_bfloat16 Ah[BM][KP], Al[BM][KP];   // [m][k]
    __shared__ __nv_bfloat16 Bh[BN][KP], Bl[BN][KP];   // W^T: [n][k]

    const int tid  = threadIdx.x;
    const int lane = tid & 31;
    const int wid  = tid >> 5;
    const int row0 = blockIdx.y * BM;
    const int col0 = blockIdx.x * BN;

    const int m_off = (wid & 3) * 32;   // warp m offset inside CTA tile
    const int n_off = (wid >> 2) * 32;  // warp n offset

    float acc[2][4][4];                  // [m16 tile][n8 tile][4]
    #pragma unroll
    for (int i = 0; i < 2; i++)
        #pragma unroll
        for (int j = 0; j < 4; j++)
            #pragma unroll
            for (int r = 0; r < 4; r++) acc[i][j][r] = 0.f;

    const int lr = lane >> 2;            // 0..7
    const int lc = (lane & 3) * 2;       // 0,2,4,6

    for (int k0 = 0; k0 < K; k0 += BK) {
        // ---- stage A tile (128x32) as hi/lo bf16 ----
        #pragma unroll
        for (int i = 0; i < 4; i++) {
            int idx = tid + 256 * i;           // 0..1023 float4 slots
            int r = idx >> 3, c = (idx & 7) * 4;
            float4 v = *(const float4*)(A + (size_t)(row0 + r) * K + k0 + c);
            float vv[4] = {v.x, v.y, v.z, v.w};
            #pragma unroll
            for (int j = 0; j < 4; j++) {
                __nv_bfloat16 h = __float2bfloat16_rn(vv[j]);
                Ah[r][c + j] = h;
                Al[r][c + j] = __float2bfloat16_rn(vv[j] - __bfloat162float(h));
            }
        }
        // ---- stage W tile (32x64) transposed as hi/lo bf16 ----
        #pragma unroll
        for (int i = 0; i < 2; i++) {
            int idx = tid + 256 * i;           // 0..511 float4 slots
            int kr = idx >> 4, nc = (idx & 15) * 4;
            float4 v = *(const float4*)(W + (size_t)(k0 + kr) * N + col0 + nc);
            float vv[4] = {v.x, v.y, v.z, v.w};
            #pragma unroll
            for (int j = 0; j < 4; j++) {
                __nv_bfloat16 h = __float2bfloat16_rn(vv[j]);
                Bh[nc + j][kr] = h;
                Bl[nc + j][kr] = __float2bfloat16_rn(vv[j] - __bfloat162float(h));
            }
        }
        __syncthreads();

        #pragma unroll
        for (int ks = 0; ks < BK; ks += 16) {
            // A fragments for the warp's 2 m16 tiles
            uint32_t ah[2][4], al[2][4];
            #pragma unroll
            for (int mt = 0; mt < 2; mt++) {
                int R = m_off + mt * 16 + lr;
                int Ck = ks + lc;
                ah[mt][0] = *(const uint32_t*)&Ah[R    ][Ck    ];
                ah[mt][1] = *(const uint32_t*)&Ah[R + 8][Ck    ];
                ah[mt][2] = *(const uint32_t*)&Ah[R    ][Ck + 8];
                ah[mt][3] = *(const uint32_t*)&Ah[R + 8][Ck + 8];
                al[mt][0] = *(const uint32_t*)&Al[R    ][Ck    ];
                al[mt][1] = *(const uint32_t*)&Al[R + 8][Ck    ];
                al[mt][2] = *(const uint32_t*)&Al[R    ][Ck + 8];
                al[mt][3] = *(const uint32_t*)&Al[R + 8][Ck + 8];
            }
            // B fragments for the warp's 4 n8 tiles
            uint32_t bh[4][2], bl[4][2];
            #pragma unroll
            for (int nt = 0; nt < 4; nt++) {
                int Nn = n_off + nt * 8 + lr;
                int Ck = ks + lc;
                bh[nt][0] = *(const uint32_t*)&Bh[Nn][Ck    ];
                bh[nt][1] = *(const uint32_t*)&Bh[Nn][Ck + 8];
                bl[nt][0] = *(const uint32_t*)&Bl[Nn][Ck    ];
                bl[nt][1] = *(const uint32_t*)&Bl[Nn][Ck + 8];
            }
            #pragma unroll
            for (int mt = 0; mt < 2; mt++)
                #pragma unroll
                for (int nt = 0; nt < 4; nt++) {
                    mma16816(acc[mt][nt], ah[mt], bh[nt]);   // hi*hi
                    mma16816(acc[mt][nt], ah[mt], bl[nt]);   // hi*lo
                    mma16816(acc[mt][nt], al[mt], bh[nt]);   // lo*hi
                }
        }
        __syncthreads();
    }

    // ---- epilogue: bias + store ----
    #pragma unroll
    for (int mt = 0; mt < 2; mt++) {
        int Rg = row0 + m_off + mt * 16 + lr;
        #pragma unroll
        for (int nt = 0; nt < 4; nt++) {
            int Cg = col0 + n_off + nt * 8 + lc;
            float2 bv = *(const float2*)(bias + Cg);
            float2 v0 = make_float2(acc[mt][nt][0] + bv.x, acc[mt][nt][1] + bv.y);
            float2 v1 = make_float2(acc[mt][nt][2] + bv.x, acc[mt][nt][3] + bv.y);
            *(float2*)(C + (size_t)Rg * N + Cg)       = v0;
            *(float2*)(C + (size_t)(Rg + 8) * N + Cg) = v1;
        }
    }
}

// ---------------- causal flash attention, fp32 ---------------------------------
#define SMS 65

__global__ __launch_bounds__(256) void attn_kernel(
    const float* __restrict__ Qm,   // [NTOK, DIM]
    const float* __restrict__ KVm,  // [NTOK, 2*DIM]
    float* __restrict__ Ctx)        // [NTOK, DIM]
{
    extern __shared__ float smx[];
    float* Qs  = smx;
    float* Kts = smx + 64*SMS;
    float* Vs  = smx + 2*64*SMS;
    float* Ps  = smx + 3*64*SMS;

    const int qi  = blockIdx.x;
    const int b   = blockIdx.y >> 4;
    const int h   = blockIdx.y & 15;
    const int tid = threadIdx.x;
    const int tx  = tid & 15, ty = tid >> 4;

    const int qtok0 = b * SEQ + qi * 64;
    const float* Qbase = Qm + (size_t)qtok0 * DIM + h * HD;

    for (int idx = tid; idx < 4096; idx += 256) {
        int r = idx >> 6, d = idx & 63;
        Qs[r*SMS + d] = Qbase[(size_t)r * DIM + d];
    }

    float m_run[4], l_run[4], o[4][4];
    #pragma unroll
    for (int i = 0; i < 4; i++) {
        m_run[i] = -INFINITY; l_run[i] = 0.f;
        #pragma unroll
        for (int j = 0; j < 4; j++) o[i][j] = 0.f;
    }

    for (int kt = 0; kt <= qi; kt++) {
        const float* Kbase = KVm + (size_t)(b * SEQ + kt * 64) * (2*DIM) + h * HD;
        const float* Vbase = Kbase + DIM;
        for (int idx = tid; idx < 4096; idx += 256) {
            int r = idx >> 6, d = idx & 63;
            Kts[d*SMS + r] = Kbase[(size_t)r * (2*DIM) + d];
            Vs [r*SMS + d] = Vbase[(size_t)r * (2*DIM) + d];
        }
        __syncthreads();

        float s[4][4] = {};
        #pragma unroll 8
        for (int d = 0; d < 64; d++) {
            float a0 = Qs[(ty*4+0)*SMS + d];
            float a1 = Qs[(ty*4+1)*SMS + d];
            float a2 = Qs[(ty*4+2)*SMS + d];
            float a3 = Qs[(ty*4+3)*SMS + d];
            float b0 = Kts[d*SMS + tx*4+0];
            float b1 = Kts[d*SMS + tx*4+1];
            float b2 = Kts[d*SMS + tx*4+2];
            float b3 = Kts[d*SMS + tx*4+3];
            s[0][0] = fmaf(a0,b0,s[0][0]); s[0][1] = fmaf(a0,b1,s[0][1]);
            s[0][2] = fmaf(a0,b2,s[0][2]); s[0][3] = fmaf(a0,b3,s[0][3]);
            s[1][0] = fmaf(a1,b0,s[1][0]); s[1][1] = fmaf(a1,b1,s[1][1]);
            s[1][2] = fmaf(a1,b2,s[1][2]); s[1][3] = fmaf(a1,b3,s[1][3]);
            s[2][0] = fmaf(a2,b0,s[2][0]); s[2][1] = fmaf(a2,b1,s[2][1]);
            s[2][2] = fmaf(a2,b2,s[2][2]); s[2][3] = fmaf(a2,b3,s[2][3]);
            s[3][0] = fmaf(a3,b0,s[3][0]); s[3][1] = fmaf(a3,b1,s[3][1]);
            s[3][2] = fmaf(a3,b2,s[3][2]); s[3][3] = fmaf(a3,b3,s[3][3]);
        }

        const float scale = 0.125f;
        const bool diag = (kt == qi);
        #pragma unroll
        for (int i = 0; i < 4; i++) {
            int ri = ty*4 + i;
            #pragma unroll
            for (int j = 0; j < 4; j++) {
                float v = s[i][j] * scale;
                if (diag && (tx*4 + j) > ri) v = -1e30f;
                s[i][j] = v;
            }
        }

        #pragma unroll
        for (int i = 0; i < 4; i++) {
            float mx = fmaxf(fmaxf(s[i][0], s[i][1]), fmaxf(s[i][2], s[i][3]));
            mx = fmaxf(mx, __shfl_xor_sync(0xffffffffu, mx, 1));
            mx = fmaxf(mx, __shfl_xor_sync(0xffffffffu, mx, 2));
            mx = fmaxf(mx, __shfl_xor_sync(0xffffffffu, mx, 4));
            mx = fmaxf(mx, __shfl_xor_sync(0xffffffffu, mx, 8));
            float m_new = fmaxf(m_run[i], mx);
            float corr  = __expf(m_run[i] - m_new);
            m_run[i] = m_new;
            float psum = 0.f;
            #pragma unroll
            for (int j = 0; j < 4; j++) {
                float p = __expf(s[i][j] - m_new);
                s[i][j] = p;
                psum += p;
            }
            psum += __shfl_xor_sync(0xffffffffu, psum, 1);
            psum += __shfl_xor_sync(0xffffffffu, psum, 2);
            psum += __shfl_xor_sync(0xffffffffu, psum, 4);
            psum += __shfl_xor_sync(0xffffffffu, psum, 8);
            l_run[i] = l_run[i] * corr + psum;
            #pragma unroll
            for (int j = 0; j < 4; j++) o[i][j] *= corr;
        }

        #pragma unroll
        for (int i = 0; i < 4; i++)
            #pragma unroll
            for (int j = 0; j < 4; j++)
                Ps[(ty*4+i)*SMS + tx*4+j] = s[i][j];
        __syncthreads();

        #pragma unroll 8
        for (int kk = 0; kk < 64; kk++) {
            float a0 = Ps[(ty*4+0)*SMS + kk];
            float a1 = Ps[(ty*4+1)*SMS + kk];
            float a2 = Ps[(ty*4+2)*SMS + kk];
            float a3 = Ps[(ty*4+3)*SMS + kk];
            float b0 = Vs[kk*SMS + tx*4+0];
            float b1 = Vs[kk*SMS + tx*4+1];
            float b2 = Vs[kk*SMS + tx*4+2];
            float b3 = Vs[kk*SMS + tx*4+3];
            o[0][0] = fmaf(a0,b0,o[0][0]); o[0][1] = fmaf(a0,b1,o[0][1]);
            o[0][2] = fmaf(a0,b2,o[0][2]); o[0][3] = fmaf(a0,b3,o[0][3]);
            o[1][0] = fmaf(a1,b0,o[1][0]); o[1][1] = fmaf(a1,b1,o[1][1]);
            o[1][2] = fmaf(a1,b2,o[1][2]); o[1][3] = fmaf(a1,b3,o[1][3]);
            o[2][0] = fmaf(a2,b0,o[2][0]); o[2][1] = fmaf(a2,b1,o[2][1]);
            o[2][2] = fmaf(a2,b2,o[2][2]); o[2][3] = fmaf(a2,b3,o[2][3]);
            o[3][0] = fmaf(a3,b0,o[3][0]); o[3][1] = fmaf(a3,b1,o[3][1]);
            o[3][2] = fmaf(a3,b2,o[3][2]); o[3][3] = fmaf(a3,b3,o[3][3]);
        }
        __syncthreads();
    }

    float* Cbase = Ctx + (size_t)qtok0 * DIM + h * HD;
    #pragma unroll
    for (int i = 0; i < 4; i++) {
        float inv = 1.f / l_run[i];
        float4 ov = make_float4(o[i][0]*inv, o[i][1]*inv, o[i][2]*inv, o[i][3]*inv);
        *(float4*)(Cbase + (size_t)(ty*4 + i) * DIM + tx*4) = ov;
    }
}

// ---------------- launch --------------------------------------------------------
extern "C" void kernel_launch(void* const* d_in, const int* in_sizes, int n_in,
                              void* d_out, int out_size)
{
    const float* x     = (const float*)d_in[0];
    // d_in[1]: causal mask — implemented structurally
    const float* w_kvc = (const float*)d_in[2];
    const float* b_kvc = (const float*)d_in[3];
    const float* w_kvu = (const float*)d_in[4];
    const float* b_kvu = (const float*)d_in[5];
    const float* w_qc  = (const float*)d_in[6];
    const float* b_qc  = (const float*)d_in[7];
    const float* w_qu  = (const float*)d_in[8];
    const float* b_qu  = (const float*)d_in[9];
    const float* w_o   = (const float*)d_in[10];
    const float* b_o   = (const float*)d_in[11];
    float* out = (float*)d_out;

    float *kvl, *kvup, *qc, *q, *ctx;
    cudaGetSymbolAddress((void**)&kvl,  g_kvl);
    cudaGetSymbolAddress((void**)&kvup, g_kvup);
    cudaGetSymbolAddress((void**)&qc,   g_qc);
    cudaGetSymbolAddress((void**)&q,    g_q);
    cudaGetSymbolAddress((void**)&ctx,  g_ctx);

    const int ATTN_SMEM = 4 * 64 * SMS * (int)sizeof(float);
    cudaFuncSetAttribute(attn_kernel, cudaFuncAttributeMaxDynamicSharedMemorySize, ATTN_SMEM);

    dim3 blk(256);

    // 1) kv_latent = x @ w_kvc + b                [8192, 128]
    gemm_bf16x2<<<dim3(LATENT/BN, NTOK/BM), blk>>>(x, w_kvc, b_kvc, kvl, NTOK, LATENT, DIM);
    // 2) kv_up = kv_latent @ w_kvu + b            [8192, 2048]
    gemm_bf16x2<<<dim3(2*DIM/BN, NTOK/BM), blk>>>(kvl, w_kvu, b_kvu, kvup, NTOK, 2*DIM, LATENT);
    // 3) qc = x @ w_qc + b                        [8192, 256]
    gemm_bf16x2<<<dim3(QRANK/BN, NTOK/BM), blk>>>(x, w_qc, b_qc, qc, NTOK, QRANK, DIM);
    // 4) Q = qc @ w_qu + b                        [8192, 1024]
    gemm_bf16x2<<<dim3(DIM/BN, NTOK/BM), blk>>>(qc, w_qu, b_qu, q, NTOK, DIM, QRANK);
    // 5) causal attention -> ctx                  [8192, 1024]
    attn_kernel<<<dim3(SEQ/64, BATCH*NH), blk, ATTN_SMEM>>>(q, kvup, ctx);
    // 6) out = ctx @ w_o + b                      [8192, 1024]
    gemm_bf16x2<<<dim3(DIM/BN, NTOK/BM), blk>>>(ctx, w_o, b_o, out, NTOK, DIM, DIM);
}